// round 1
// baseline (speedup 1.0000x reference)
#include <cuda_runtime.h>
#include <math.h>

#define NB 96
#define NC 64
#define NN 512
#define NO 64

// ---------------- scratch (device globals; no allocation) ----------------
__device__ float g_x0 [NB*NC*NN];
__device__ float g_x1 [NB*NC*NN];
__device__ float g_x1e[NB*NC*NN];
__device__ float g_PQ [NB*2*NO*NN];   // per batch: rows 0..63 = P', rows 64..127 = Q'
__device__ int   g_i10[NB*NN*10];
__device__ int   g_i8 [NB*NN*8];
__device__ float g_f  [NB*NN];
__device__ float g_msk[NB*NN];

// ---------------- kernel 1: erase0 (x -> x0) + temporal shift (x -> x1seq) ----------------
__global__ __launch_bounds__(256) void k_prep(const float* __restrict__ x,
    const float* __restrict__ w_e, const float* __restrict__ b_e,
    const float* __restrict__ g_e, const float* __restrict__ be_e,
    const float* __restrict__ m_e, const float* __restrict__ v_e)
{
    int b = blockIdx.x, tid = threadIdx.x;
    __shared__ float res[NC];
    __shared__ float yb[NC];
    const float* xb = x + (size_t)b*NC*NN;

    // mean over n per channel (softmax of ones is uniform 1/512)
    int ch = tid >> 2, lane = tid & 3;
    float s = 0.f;
    for (int i = lane; i < NN; i += 4) s += xb[ch*NN + i];
    s += __shfl_down_sync(0xffffffffu, s, 1, 4);
    s += __shfl_down_sync(0xffffffffu, s, 2, 4);
    if (lane == 0) res[ch] = s * (1.0f/NN);
    __syncthreads();

    if (tid < NC) {
        float y = b_e[tid];
        for (int c = 0; c < NC; c++) y = fmaf(w_e[tid*NC + c], res[c], y);
        float sc = g_e[tid] * rsqrtf(v_e[tid] + 1e-5f);
        yb[tid] = (y - m_e[tid]) * sc + be_e[tid];
    }
    __syncthreads();

    int ti = b % 12;
    int tshift = (ti + 1 < 11) ? (ti + 1) : 11;
    int srcb = b - ti + tshift;
    const float* xsft = x + (size_t)srcb*NC*NN;
    float* x0 = g_x0 + (size_t)b*NC*NN;
    float* x1 = g_x1 + (size_t)b*NC*NN;
    for (int idx = tid; idx < NC*NN; idx += 256) {
        int c = idx >> 9;
        x0[idx] = xb[idx] + yb[c];
        x1[idx] = xsft[idx];
    }
}

// ---------------- kernel 2: fused kNN (distance Gram + top-K) ----------------
// grid (96, 3): 3-way row split per batch so 288 blocks cover 148 SMs in ~2 waves
template<int K>
__global__ __launch_bounds__(256) void k_knn(int sel)
{
    extern __shared__ float smk[];
    float* xs = smk;            // [NN][68] padded rows (272B, 16B aligned, de-conflicted)
    float* xx = smk + NN*68;    // [NN]
    const float* xin = (sel == 0) ? g_x0 : ((sel == 1) ? g_x1 : g_x1e);
    int* idxout = (K == 10) ? g_i10 : g_i8;

    int b = blockIdx.x, sp = blockIdx.y, tid = threadIdx.x;
    const float* xb = xin + (size_t)b*NC*NN;

    for (int r = tid; r < NN; r += 256) {
        float acc = 0.f;
        #pragma unroll 8
        for (int cp = 0; cp < NC; cp++) {
            float v = xb[cp*NN + r];          // coalesced across threads
            xs[r*68 + cp] = v;
            acc = fmaf(v, v, acc);
        }
        xx[r] = acc;
    }
    __syncthreads();

    int lo = (NN*sp)/3, hi = (NN*(sp+1))/3;
    int i = lo + tid;
    if (i >= hi) return;

    float4 xi[16];
    const float4* xr = (const float4*)(xs + i*68);
    #pragma unroll
    for (int m = 0; m < 16; m++) xi[m] = xr[m];
    float xxi = xx[i];

    float bv[K]; int bix[K];
    #pragma unroll
    for (int q = 0; q < K; q++) { bv[q] = -3e38f; bix[q] = 0; }

    for (int j = 0; j < NN; j++) {
        const float4* yr = (const float4*)(xs + j*68);   // warp-uniform -> LDS broadcast
        float d0 = 0.f, d1 = 0.f, d2 = 0.f, d3 = 0.f;
        #pragma unroll
        for (int m = 0; m < 16; m++) {
            float4 y = yr[m];
            d0 = fmaf(xi[m].x, y.x, d0);
            d1 = fmaf(xi[m].y, y.y, d1);
            d2 = fmaf(xi[m].z, y.z, d2);
            d3 = fmaf(xi[m].w, y.w, d3);
        }
        float pd = 2.0f*((d0+d1)+(d2+d3)) - xxi - xx[j];   // = -||xi-xj||^2
        if (pd > bv[K-1]) {                                 // rare (~40 of 512)
            float v = pd; int id = j;
            #pragma unroll
            for (int q = 0; q < K; q++) {
                if (v > bv[q]) {
                    float tv = bv[q]; int tq = bix[q];
                    bv[q] = v; bix[q] = id;
                    v = tv;  id = tq;
                }
            }
        }
    }
    int* op = idxout + ((size_t)b*NN + i)*K;
    #pragma unroll
    for (int q = 0; q < K; q++) op[q] = bix[q];
}

// ---------------- kernel 3: P'/Q' GEMM with BN folded in ----------------
// Out[b][0:64][j]   = s[o] * (wA[o] . x[:,j])                      (P')
// Out[b][64:128][j] = s[o] * ((wB-wA)[o] . x[:,j]) + (b - m*s)[o]  (Q')
__global__ __launch_bounds__(256) void k_pq(int sel,
    const float* __restrict__ w, const float* __restrict__ gg,
    const float* __restrict__ bb, const float* __restrict__ mm,
    const float* __restrict__ vv)
{
    extern __shared__ float smp[];
    float* xs2   = smp;            // [64][128] x tile
    float* W2    = smp + 8192;     // [128][64] fused weights
    float* bias2 = smp + 16384;    // [128]
    float* sarr  = bias2 + 128;    // [64]
    const float* xin = (sel == 0) ? g_x0 : g_x1e;

    int b = blockIdx.x, jq = blockIdx.y, tid = threadIdx.x;
    if (tid < 64) sarr[tid] = gg[tid] * rsqrtf(vv[tid] + 1e-5f);
    __syncthreads();

    for (int idx = tid; idx < 128*64; idx += 256) {
        int r = idx >> 6, c = idx & 63;
        float val;
        if (r < 64) val = sarr[r] * w[r*128 + c];
        else { int o = r - 64; val = sarr[o] * (w[o*128 + 64 + c] - w[o*128 + c]); }
        W2[idx] = val;
    }
    if (tid < 128)
        bias2[tid] = (tid < 64) ? 0.f : (bb[tid-64] - mm[tid-64]*sarr[tid-64]);

    const float* xb = xin + (size_t)b*NC*NN + jq*128;
    for (int idx = tid; idx < 64*128; idx += 256) {
        int c = idx >> 7, jj = idx & 127;
        xs2[idx] = xb[c*NN + jj];
    }
    __syncthreads();

    int rt = tid >> 4, ct = tid & 15;
    int r0 = rt*8, j0 = ct*8;
    float acc[8][8];
    #pragma unroll
    for (int u = 0; u < 8; u++)
        #pragma unroll
        for (int v = 0; v < 8; v++) acc[u][v] = 0.f;

    for (int kk = 0; kk < 64; kk++) {
        float wv[8];
        #pragma unroll
        for (int u = 0; u < 8; u++) wv[u] = W2[(r0+u)*64 + kk];
        float4 xa  = *(const float4*)(xs2 + kk*128 + j0);
        float4 xb4 = *(const float4*)(xs2 + kk*128 + j0 + 4);
        float xv[8] = {xa.x, xa.y, xa.z, xa.w, xb4.x, xb4.y, xb4.z, xb4.w};
        #pragma unroll
        for (int u = 0; u < 8; u++)
            #pragma unroll
            for (int v = 0; v < 8; v++) acc[u][v] = fmaf(wv[u], xv[v], acc[u][v]);
    }

    float* outp = g_PQ + (size_t)b*128*NN + jq*128;
    #pragma unroll
    for (int u = 0; u < 8; u++) {
        float bsv = bias2[r0+u];
        float4 o0 = make_float4(acc[u][0]+bsv, acc[u][1]+bsv, acc[u][2]+bsv, acc[u][3]+bsv);
        float4 o1 = make_float4(acc[u][4]+bsv, acc[u][5]+bsv, acc[u][6]+bsv, acc[u][7]+bsv);
        *(float4*)(outp + (r0+u)*NN + j0)     = o0;
        *(float4*)(outp + (r0+u)*NN + j0 + 4) = o1;
    }
}

// ---------------- kernel 4: gather-max over k + lrelu + max/mean over n ----------------
__global__ __launch_bounds__(256) void k_gmax(float* __restrict__ out, int accumulate)
{
    extern __shared__ float smg[];
    float* Ps = smg;                    // [64][512]
    int* ids  = (int*)(smg + 64*NN);    // [512][10]
    int b = blockIdx.x, tid = threadIdx.x;
    const float* Pg = g_PQ + (size_t)b*128*NN;
    for (int t = tid; t < 64*NN; t += 256) Ps[t] = Pg[t];
    const int* ig = g_i10 + (size_t)b*NN*10;
    for (int t = tid; t < NN*10; t += 256) ids[t] = ig[t];
    __syncthreads();

    int o = tid >> 2, sub = tid & 3;
    const float* Qrow = Pg + (size_t)(64 + o)*NN;
    const float* Po = Ps + o*NN;
    float lmax = -3e38f, lsum = 0.f;
    for (int i = sub; i < NN; i += 4) {
        const int* ip = ids + i*10;
        float mx = -3e38f;
        #pragma unroll
        for (int kk = 0; kk < 10; kk++) mx = fmaxf(mx, Po[ip[kk]]);
        float y = mx + Qrow[i];
        y = (y > 0.f) ? y : 0.2f*y;      // lrelu(max) == max(lrelu): monotone
        lmax = fmaxf(lmax, y);
        lsum += y;
    }
    lmax = fmaxf(lmax, __shfl_down_sync(0xffffffffu, lmax, 1, 4));
    lmax = fmaxf(lmax, __shfl_down_sync(0xffffffffu, lmax, 2, 4));
    lsum += __shfl_down_sync(0xffffffffu, lsum, 1, 4);
    lsum += __shfl_down_sync(0xffffffffu, lsum, 2, 4);
    if (sub == 0) {
        float* ob = out + b*128;
        float pm = lmax, pa = lsum*(1.0f/NN);
        if (accumulate) { ob[o] += pm; ob[64+o] += pa; }
        else            { ob[o]  = pm; ob[64+o]  = pa; }
    }
}

// ---------------- kernel 5: corre_binar (q, f, fk, argmax, masks) ----------------
// fk[i] = f[i] + sum_k f[idx8[i,k]]   (since q.neigh*scale == f at neighbor index)
__global__ __launch_bounds__(512) void k_corre(const float* __restrict__ w_red,
                                               const float* __restrict__ outv)
{
    __shared__ float qv[64];
    __shared__ float fs[NN];
    __shared__ float rv[NN];
    __shared__ int   ri[NN];
    int b = blockIdx.x, tid = threadIdx.x;
    if (tid < 64) {
        const float* xv = outv + b*128;    // x0_vec == p0 max-half (written by gmax0)
        float a = 0.f;
        for (int c = 0; c < 64; c++) a = fmaf(w_red[tid*64 + c], xv[c], a);
        qv[tid] = a;
    }
    __syncthreads();
    const float* x1b = g_x1 + (size_t)b*NC*NN;
    float f = 0.f;
    for (int c = 0; c < 64; c++) f = fmaf(qv[c], x1b[c*NN + tid], f);
    f *= 0.125f;                            // 1/sqrt(64)
    fs[tid] = f;
    g_f[b*NN + tid] = f;
    __syncthreads();
    const int* i8 = g_i8 + ((size_t)b*NN + tid)*8;
    float fk = f;
    #pragma unroll
    for (int kk = 0; kk < 8; kk++) fk += fs[i8[kk]];
    rv[tid] = fk; ri[tid] = tid;
    __syncthreads();
    for (int s2 = 256; s2 > 0; s2 >>= 1) {   // argmax, ties -> lowest index
        if (tid < s2) {
            float a = rv[tid], b2 = rv[tid + s2];
            int ia = ri[tid], ib2 = ri[tid + s2];
            if (b2 > a || (b2 == a && ib2 < ia)) { rv[tid] = b2; ri[tid] = ib2; }
        }
        __syncthreads();
    }
    int widx = ri[0];
    g_msk[b*NN + tid] = 1.0f;
    __syncthreads();
    if (tid == 0) g_msk[b*NN + widx] = 0.f;
    if (tid < 8)  g_msk[b*NN + g_i8[((size_t)b*NN + widx)*8 + tid]] = 0.f;
}

// ---------------- kernel 6: erase1 (masked softmax attention + conv_erase) ----------------
__global__ __launch_bounds__(512) void k_erase1(
    const float* __restrict__ w_e, const float* __restrict__ b_e,
    const float* __restrict__ g_e, const float* __restrict__ be_e,
    const float* __restrict__ m_e, const float* __restrict__ v_e)
{
    __shared__ float smw[NN];
    __shared__ float red[NN];
    __shared__ float msk[NN];
    __shared__ float res[64];
    __shared__ float yb[64];
    int b = blockIdx.x, tid = threadIdx.x;
    const float* x1b = g_x1 + (size_t)b*NC*NN;

    float M = g_msk[b*NN + tid];
    float f = g_f[b*NN + tid];
    msk[tid] = M;
    float z = f - (1.0f - M)*1e8f;
    red[tid] = z;
    __syncthreads();
    for (int s2 = 256; s2 > 0; s2 >>= 1) {
        if (tid < s2) red[tid] = fmaxf(red[tid], red[tid + s2]);
        __syncthreads();
    }
    float zmax = red[0];
    __syncthreads();
    float e = expf(z - zmax);
    red[tid] = e;
    __syncthreads();
    for (int s2 = 256; s2 > 0; s2 >>= 1) {
        if (tid < s2) red[tid] += red[tid + s2];
        __syncthreads();
    }
    float esum = red[0];
    smw[tid] = e / esum;
    __syncthreads();

    int ch = tid >> 3, ln = tid & 7;
    float a = 0.f;
    for (int i = ln; i < NN; i += 8) a = fmaf(x1b[ch*NN + i], smw[i], a);
    a += __shfl_down_sync(0xffffffffu, a, 1, 8);
    a += __shfl_down_sync(0xffffffffu, a, 2, 8);
    a += __shfl_down_sync(0xffffffffu, a, 4, 8);
    if (ln == 0) res[ch] = a;
    __syncthreads();

    if (tid < 64) {
        float y = b_e[tid];
        for (int c = 0; c < 64; c++) y = fmaf(w_e[tid*64 + c], res[c], y);
        float sc = g_e[tid]*rsqrtf(v_e[tid] + 1e-5f);
        yb[tid] = (y - m_e[tid])*sc + be_e[tid];
    }
    __syncthreads();

    float* xo = g_x1e + (size_t)b*NC*NN;
    for (int idx = tid; idx < NC*NN; idx += 512) {
        int c = idx >> 9, i = idx & 511;
        xo[idx] = x1b[idx]*msk[i] + yb[c];
    }
}

// ---------------- launcher ----------------
extern "C" void kernel_launch(void* const* d_in, const int* in_sizes, int n_in,
                              void* d_out, int out_size)
{
    const float* x        = (const float*)d_in[0];
    const float* w_reduce = (const float*)d_in[1];
    const float* w_erase  = (const float*)d_in[2];
    const float* b_erase  = (const float*)d_in[3];
    const float* g_erase  = (const float*)d_in[4];
    const float* be_erase = (const float*)d_in[5];
    const float* m_erase  = (const float*)d_in[6];
    const float* v_erase  = (const float*)d_in[7];
    const float* w0 = (const float*)d_in[8];
    const float* g0 = (const float*)d_in[9];
    const float* b0 = (const float*)d_in[10];
    const float* m0 = (const float*)d_in[11];
    const float* v0 = (const float*)d_in[12];
    const float* w1 = (const float*)d_in[13];
    const float* g1 = (const float*)d_in[14];
    const float* b1 = (const float*)d_in[15];
    const float* m1 = (const float*)d_in[16];
    const float* v1 = (const float*)d_in[17];
    float* out = (float*)d_out;

    const int KNN_SMEM  = (NN*68 + NN)*4;              // 141312 B
    const int PQ_SMEM   = (8192 + 8192 + 128 + 64)*4;  // 65792 B
    const int GMAX_SMEM = 64*NN*4 + NN*10*4;           // 151552 B
    cudaFuncSetAttribute(k_knn<10>, cudaFuncAttributeMaxDynamicSharedMemorySize, KNN_SMEM);
    cudaFuncSetAttribute(k_knn<8>,  cudaFuncAttributeMaxDynamicSharedMemorySize, KNN_SMEM);
    cudaFuncSetAttribute(k_pq,      cudaFuncAttributeMaxDynamicSharedMemorySize, PQ_SMEM);
    cudaFuncSetAttribute(k_gmax,    cudaFuncAttributeMaxDynamicSharedMemorySize, GMAX_SMEM);

    k_prep<<<NB, 256>>>(x, w_erase, b_erase, g_erase, be_erase, m_erase, v_erase);
    k_knn<10><<<dim3(NB,3), 256, KNN_SMEM>>>(0);               // knn on x0
    k_pq<<<dim3(NB,4), 256, PQ_SMEM>>>(0, w0, g0, b0, m0, v0); // branch0 P/Q
    k_gmax<<<NB, 256, GMAX_SMEM>>>(out, 0);                    // p0 -> out (also x0_vec)
    k_knn<8><<<dim3(NB,3), 256, KNN_SMEM>>>(1);                // knn on x1seq
    k_corre<<<NB, 512>>>(w_reduce, out);                       // masks, f
    k_erase1<<<NB, 512>>>(w_erase, b_erase, g_erase, be_erase, m_erase, v_erase);
    k_knn<10><<<dim3(NB,3), 256, KNN_SMEM>>>(2);               // knn on x1e
    k_pq<<<dim3(NB,4), 256, PQ_SMEM>>>(2, w1, g1, b1, m1, v1); // branch1 P/Q
    k_gmax<<<NB, 256, GMAX_SMEM>>>(out, 1);                    // out += p1
}

// round 4
// speedup vs baseline: 1.2243x; 1.2243x over previous
#include <cuda_runtime.h>
#include <math.h>

#define NB 96
#define NC 64
#define NN 512
#define NO 64

// ---------------- scratch (device globals; no allocation) ----------------
__device__ float g_x0 [NB*NC*NN];
__device__ float g_x1 [NB*NC*NN];
__device__ float g_x1e[NB*NC*NN];
__device__ float g_PQ [NB*2*NO*NN];   // per batch: Pt[512][64] then Qt[512][64]
__device__ int   g_i10[NB*NN*10];
__device__ int   g_i8 [NB*NN*8];
__device__ float g_f  [NB*NN];
__device__ float g_msk[NB*NN];
__device__ float g_part[NB*4*128];    // per (b, jq): 0..63 max, 64..127 sum

// ---------------- f32x2 helpers (SASS FFMA2 — PTX-only) ----------------
__device__ __forceinline__ void fma2(unsigned long long& acc, unsigned long long a,
                                     unsigned long long b) {
    asm("fma.rn.f32x2 %0, %1, %2, %0;" : "+l"(acc) : "l"(a), "l"(b));
}
__device__ __forceinline__ unsigned long long pk2(float lo, float hi) {
    unsigned long long r;
    asm("mov.b64 %0, {%1, %2};" : "=l"(r) : "f"(lo), "f"(hi));
    return r;
}
__device__ __forceinline__ float2 upk(unsigned long long v) {
    float2 r;
    asm("mov.b64 {%0, %1}, %2;" : "=f"(r.x), "=f"(r.y) : "l"(v));
    return r;
}

// ---------------- kernel 1: erase0 (x -> x0) + temporal shift (x -> x1seq) ----------------
__global__ __launch_bounds__(256) void k_prep(const float* __restrict__ x,
    const float* __restrict__ w_e, const float* __restrict__ b_e,
    const float* __restrict__ g_e, const float* __restrict__ be_e,
    const float* __restrict__ m_e, const float* __restrict__ v_e)
{
    int b = blockIdx.x, tid = threadIdx.x;
    __shared__ float res[NC];
    __shared__ float yb[NC];
    const float* xb = x + (size_t)b*NC*NN;

    int ch = tid >> 2, lane = tid & 3;
    float s = 0.f;
    for (int i = lane; i < NN; i += 4) s += xb[ch*NN + i];
    s += __shfl_down_sync(0xffffffffu, s, 1, 4);
    s += __shfl_down_sync(0xffffffffu, s, 2, 4);
    if (lane == 0) res[ch] = s * (1.0f/NN);
    __syncthreads();

    if (tid < NC) {
        float y = b_e[tid];
        for (int c = 0; c < NC; c++) y = fmaf(w_e[tid*NC + c], res[c], y);
        float sc = g_e[tid] * rsqrtf(v_e[tid] + 1e-5f);
        yb[tid] = (y - m_e[tid]) * sc + be_e[tid];
    }
    __syncthreads();

    int ti = b % 12;
    int tshift = (ti + 1 < 11) ? (ti + 1) : 11;
    int srcb = b - ti + tshift;
    const float* xsft = x + (size_t)srcb*NC*NN;
    float* x0 = g_x0 + (size_t)b*NC*NN;
    float* x1 = g_x1 + (size_t)b*NC*NN;
    for (int idx = tid; idx < NC*NN; idx += 256) {
        int c = idx >> 9;
        x0[idx] = xb[idx] + yb[c];
        x1[idx] = xsft[idx];
    }
}

// ---------------- kernel 2: fused kNN (Gram + top-K) with FFMA2 ----------------
// grid (96, 3), 192 threads: 3-way row split, every thread owns one query point
template<int K>
__global__ __launch_bounds__(192) void k_knn(int sel)
{
    extern __shared__ float smk[];
    float* xs = smk;            // [NN][68] padded rows (272B, 16B aligned)
    float* xx = smk + NN*68;    // [NN]
    const float* xin = (sel == 0) ? g_x0 : ((sel == 1) ? g_x1 : g_x1e);
    int* idxout = (K == 10) ? g_i10 : g_i8;

    int b = blockIdx.x, sp = blockIdx.y, tid = threadIdx.x;
    const float* xb = xin + (size_t)b*NC*NN;

    for (int r = tid; r < NN; r += 192) {
        float acc = 0.f;
        #pragma unroll 8
        for (int cp = 0; cp < NC; cp++) {
            float v = xb[cp*NN + r];
            xs[r*68 + cp] = v;
            acc = fmaf(v, v, acc);
        }
        xx[r] = acc;
    }
    __syncthreads();

    int lo = (NN*sp)/3, hi = (NN*(sp+1))/3;
    int i = lo + tid;
    if (i >= hi) return;

    unsigned long long xiu[32];
    {
        const ulonglong2* xr = (const ulonglong2*)(xs + i*68);
        #pragma unroll
        for (int m = 0; m < 16; m++) {
            ulonglong2 t = xr[m];
            xiu[2*m]   = t.x;
            xiu[2*m+1] = t.y;
        }
    }
    float xxi = xx[i];

    float bv[K]; int bix[K];
    #pragma unroll
    for (int q = 0; q < K; q++) { bv[q] = -3e38f; bix[q] = 0; }

    for (int j = 0; j < NN; j++) {
        const ulonglong2* yr = (const ulonglong2*)(xs + j*68);  // warp-uniform broadcast
        unsigned long long a0 = 0ull, a1 = 0ull, a2 = 0ull, a3 = 0ull;
        #pragma unroll
        for (int m = 0; m < 16; m += 2) {
            ulonglong2 y0 = yr[m];
            ulonglong2 y1 = yr[m+1];
            fma2(a0, xiu[2*m],   y0.x);
            fma2(a1, xiu[2*m+1], y0.y);
            fma2(a2, xiu[2*m+2], y1.x);
            fma2(a3, xiu[2*m+3], y1.y);
        }
        float2 f0 = upk(a0), f1 = upk(a1), f2 = upk(a2), f3 = upk(a3);
        float dot = ((f0.x+f0.y)+(f1.x+f1.y)) + ((f2.x+f2.y)+(f3.x+f3.y));
        float pd = 2.0f*dot - xxi - xx[j];               // = -||xi-xj||^2
        if (pd > bv[K-1]) {                              // rare (~K/j on average)
            float v = pd; int id = j;
            #pragma unroll
            for (int q = 0; q < K; q++) {
                if (v > bv[q]) {
                    float tv = bv[q]; int tq = bix[q];
                    bv[q] = v; bix[q] = id;
                    v = tv;  id = tq;
                }
            }
        }
    }
    int* op = idxout + ((size_t)b*NN + i)*K;
    #pragma unroll
    for (int q = 0; q < K; q++) op[q] = bix[q];
}

// ---------------- kernel 3: P'/Q' GEMM (BN folded), FFMA2, TRANSPOSED output ----------------
// Pt[j][o] = s[o]*(wA[o].x_j) ; Qt[j][o] = s[o]*((wB-wA)[o].x_j) + (b - m*s)[o]
__global__ __launch_bounds__(256) void k_pq(int sel,
    const float* __restrict__ w, const float* __restrict__ gg,
    const float* __restrict__ bb, const float* __restrict__ mm,
    const float* __restrict__ vv)
{
    extern __shared__ float smp[];
    float* xs2   = smp;            // [64][128] x tile
    float* W2    = smp + 8192;     // [128][64] fused weights
    float* bias2 = smp + 16384;    // [128]
    float* sarr  = bias2 + 128;    // [64]
    const float* xin = (sel == 0) ? g_x0 : g_x1e;

    int b = blockIdx.x, jq = blockIdx.y, tid = threadIdx.x;
    if (tid < 64) sarr[tid] = gg[tid] * rsqrtf(vv[tid] + 1e-5f);
    __syncthreads();

    for (int idx = tid; idx < 128*64; idx += 256) {
        int r = idx >> 6, c = idx & 63;
        float val;
        if (r < 64) val = sarr[r] * w[r*128 + c];
        else { int o = r - 64; val = sarr[o] * (w[o*128 + 64 + c] - w[o*128 + c]); }
        W2[idx] = val;
    }
    if (tid < 128)
        bias2[tid] = (tid < 64) ? 0.f : (bb[tid-64] - mm[tid-64]*sarr[tid-64]);

    const float* xb = xin + (size_t)b*NC*NN + jq*128;
    for (int idx = tid; idx < 64*128; idx += 256) {
        int c = idx >> 7, jj = idx & 127;
        xs2[idx] = xb[c*NN + jj];
    }
    __syncthreads();

    int rt = tid >> 4, ct = tid & 15;
    int r0 = rt*8, j0 = ct*8;
    unsigned long long accp[8][4];
    #pragma unroll
    for (int u = 0; u < 8; u++)
        #pragma unroll
        for (int vp = 0; vp < 4; vp++) accp[u][vp] = 0ull;

    for (int kk = 0; kk < 64; kk++) {
        unsigned long long wp[8];
        #pragma unroll
        for (int u = 0; u < 8; u++) {
            float wv = W2[(r0+u)*64 + kk];
            wp[u] = pk2(wv, wv);
        }
        const ulonglong2* xp = (const ulonglong2*)(xs2 + kk*128 + j0);
        ulonglong2 xa = xp[0], xc = xp[1];
        #pragma unroll
        for (int u = 0; u < 8; u++) {
            fma2(accp[u][0], wp[u], xa.x);
            fma2(accp[u][1], wp[u], xa.y);
            fma2(accp[u][2], wp[u], xc.x);
            fma2(accp[u][3], wp[u], xc.y);
        }
    }

    // unpack + bias, then transposed store
    float a[8][8];
    #pragma unroll
    for (int u = 0; u < 8; u++) {
        float bsv = bias2[r0+u];
        #pragma unroll
        for (int vp = 0; vp < 4; vp++) {
            float2 t = upk(accp[u][vp]);
            a[u][2*vp]   = t.x + bsv;
            a[u][2*vp+1] = t.y + bsv;
        }
    }

    float* Ptb = g_PQ + (size_t)b*2*NO*NN;      // [512][64]
    float* Qtb = Ptb + (size_t)NN*NO;           // [512][64]
    #pragma unroll
    for (int v = 0; v < 8; v++) {
        int j = jq*128 + j0 + v;
        float* dst = (r0 < 64) ? (Ptb + (size_t)j*64 + r0)
                               : (Qtb + (size_t)j*64 + (r0-64));
        float4 o0 = make_float4(a[0][v], a[1][v], a[2][v], a[3][v]);
        float4 o1 = make_float4(a[4][v], a[5][v], a[6][v], a[7][v]);
        *(float4*)(dst)     = o0;
        *(float4*)(dst + 4) = o1;
    }
}

// ---------------- kernel 4: gather-max over k + lrelu + partial max/mean ----------------
// grid (96, 4), 256 threads. warp-per-point, lane owns 2 channels; gathers hit L2.
__global__ __launch_bounds__(256) void k_gmax()
{
    int b = blockIdx.x, jq = blockIdx.y, tid = threadIdx.x;
    int w = tid >> 5, l = tid & 31;
    const float* Pt = g_PQ + (size_t)b*2*NO*NN;
    const float* Qt = Pt + (size_t)NN*NO;
    const int* ig = g_i10 + (size_t)b*NN*10;

    float mx0 = -3e38f, mx1 = -3e38f, s0 = 0.f, s1 = 0.f;
    #pragma unroll 2
    for (int p = 0; p < 16; p++) {
        int i = jq*128 + w*16 + p;
        const int* ip = ig + (size_t)i*10;
        float a0 = -3e38f, a1 = -3e38f;
        #pragma unroll
        for (int kk = 0; kk < 10; kk++) {
            int nb = ip[kk];                               // uniform -> broadcast
            float2 pv = *(const float2*)(Pt + (size_t)nb*64 + 2*l);
            a0 = fmaxf(a0, pv.x);
            a1 = fmaxf(a1, pv.y);
        }
        float2 q = *(const float2*)(Qt + (size_t)i*64 + 2*l);
        float y0 = a0 + q.x; y0 = (y0 > 0.f) ? y0 : 0.2f*y0;
        float y1 = a1 + q.y; y1 = (y1 > 0.f) ? y1 : 0.2f*y1;
        mx0 = fmaxf(mx0, y0); s0 += y0;
        mx1 = fmaxf(mx1, y1); s1 += y1;
    }

    __shared__ float sred[8][128];
    sred[w][2*l]      = mx0;
    sred[w][2*l+1]    = mx1;
    sred[w][64+2*l]   = s0;
    sred[w][64+2*l+1] = s1;
    __syncthreads();
    if (tid < 128) {
        float v;
        if (tid < 64) {
            v = sred[0][tid];
            #pragma unroll
            for (int ww = 1; ww < 8; ww++) v = fmaxf(v, sred[ww][tid]);
        } else {
            v = sred[0][tid];
            #pragma unroll
            for (int ww = 1; ww < 8; ww++) v += sred[ww][tid];
        }
        g_part[((size_t)b*4 + jq)*128 + tid] = v;
    }
}

// ---------------- kernel 4b: final reduction over the 4 point-chunks ----------------
__global__ __launch_bounds__(128) void k_fin(float* __restrict__ out, int accumulate)
{
    int b = blockIdx.x, tid = threadIdx.x;
    const float* pp = g_part + (size_t)b*4*128;
    float v;
    if (tid < 64) {
        v = pp[tid];
        #pragma unroll
        for (int jq = 1; jq < 4; jq++) v = fmaxf(v, pp[jq*128 + tid]);
    } else {
        v = pp[tid];
        #pragma unroll
        for (int jq = 1; jq < 4; jq++) v += pp[jq*128 + tid];
        v *= (1.0f/NN);
    }
    if (accumulate) out[b*128 + tid] += v;
    else            out[b*128 + tid]  = v;
}

// ---------------- kernel 5: corre_binar (q, f, fk, argmax, masks) ----------------
__global__ __launch_bounds__(512) void k_corre(const float* __restrict__ w_red,
                                               const float* __restrict__ outv)
{
    __shared__ float qv[64];
    __shared__ float fs[NN];
    __shared__ float rv[NN];
    __shared__ int   ri[NN];
    int b = blockIdx.x, tid = threadIdx.x;
    if (tid < 64) {
        const float* xv = outv + b*128;    // x0_vec == p0 max-half
        float a = 0.f;
        for (int c = 0; c < 64; c++) a = fmaf(w_red[tid*64 + c], xv[c], a);
        qv[tid] = a;
    }
    __syncthreads();
    const float* x1b = g_x1 + (size_t)b*NC*NN;
    float f = 0.f;
    for (int c = 0; c < 64; c++) f = fmaf(qv[c], x1b[c*NN + tid], f);
    f *= 0.125f;
    fs[tid] = f;
    g_f[b*NN + tid] = f;
    __syncthreads();
    const int* i8 = g_i8 + ((size_t)b*NN + tid)*8;
    float fk = f;
    #pragma unroll
    for (int kk = 0; kk < 8; kk++) fk += fs[i8[kk]];
    rv[tid] = fk; ri[tid] = tid;
    __syncthreads();
    for (int s2 = 256; s2 > 0; s2 >>= 1) {   // argmax, ties -> lowest index
        if (tid < s2) {
            float a = rv[tid], b2 = rv[tid + s2];
            int ia = ri[tid], ib2 = ri[tid + s2];
            if (b2 > a || (b2 == a && ib2 < ia)) { rv[tid] = b2; ri[tid] = ib2; }
        }
        __syncthreads();
    }
    int widx = ri[0];
    g_msk[b*NN + tid] = 1.0f;
    __syncthreads();
    if (tid == 0) g_msk[b*NN + widx] = 0.f;
    if (tid < 8)  g_msk[b*NN + g_i8[((size_t)b*NN + widx)*8 + tid]] = 0.f;
}

// ---------------- kernel 6: erase1 (masked softmax attention + conv_erase) ----------------
__global__ __launch_bounds__(512) void k_erase1(
    const float* __restrict__ w_e, const float* __restrict__ b_e,
    const float* __restrict__ g_e, const float* __restrict__ be_e,
    const float* __restrict__ m_e, const float* __restrict__ v_e)
{
    __shared__ float smw[NN];
    __shared__ float red[NN];
    __shared__ float msk[NN];
    __shared__ float res[64];
    __shared__ float yb[64];
    int b = blockIdx.x, tid = threadIdx.x;
    const float* x1b = g_x1 + (size_t)b*NC*NN;

    float M = g_msk[b*NN + tid];
    float f = g_f[b*NN + tid];
    msk[tid] = M;
    float z = f - (1.0f - M)*1e8f;
    red[tid] = z;
    __syncthreads();
    for (int s2 = 256; s2 > 0; s2 >>= 1) {
        if (tid < s2) red[tid] = fmaxf(red[tid], red[tid + s2]);
        __syncthreads();
    }
    float zmax = red[0];
    __syncthreads();
    float e = expf(z - zmax);
    red[tid] = e;
    __syncthreads();
    for (int s2 = 256; s2 > 0; s2 >>= 1) {
        if (tid < s2) red[tid] += red[tid + s2];
        __syncthreads();
    }
    float esum = red[0];
    smw[tid] = e / esum;
    __syncthreads();

    int ch = tid >> 3, ln = tid & 7;
    float a = 0.f;
    for (int i = ln; i < NN; i += 8) a = fmaf(x1b[ch*NN + i], smw[i], a);
    a += __shfl_down_sync(0xffffffffu, a, 1, 8);
    a += __shfl_down_sync(0xffffffffu, a, 2, 8);
    a += __shfl_down_sync(0xffffffffu, a, 4, 8);
    if (ln == 0) res[ch] = a;
    __syncthreads();

    if (tid < 64) {
        float y = b_e[tid];
        for (int c = 0; c < 64; c++) y = fmaf(w_e[tid*64 + c], res[c], y);
        float sc = g_e[tid]*rsqrtf(v_e[tid] + 1e-5f);
        yb[tid] = (y - m_e[tid])*sc + be_e[tid];
    }
    __syncthreads();

    float* xo = g_x1e + (size_t)b*NC*NN;
    for (int idx = tid; idx < NC*NN; idx += 512) {
        int c = idx >> 9, i = idx & 511;
        xo[idx] = x1b[idx]*msk[i] + yb[c];
    }
}

// ---------------- launcher ----------------
extern "C" void kernel_launch(void* const* d_in, const int* in_sizes, int n_in,
                              void* d_out, int out_size)
{
    const float* x        = (const float*)d_in[0];
    const float* w_reduce = (const float*)d_in[1];
    const float* w_erase  = (const float*)d_in[2];
    const float* b_erase  = (const float*)d_in[3];
    const float* g_erase  = (const float*)d_in[4];
    const float* be_erase = (const float*)d_in[5];
    const float* m_erase  = (const float*)d_in[6];
    const float* v_erase  = (const float*)d_in[7];
    const float* w0 = (const float*)d_in[8];
    const float* g0 = (const float*)d_in[9];
    const float* b0 = (const float*)d_in[10];
    const float* m0 = (const float*)d_in[11];
    const float* v0 = (const float*)d_in[12];
    const float* w1 = (const float*)d_in[13];
    const float* g1 = (const float*)d_in[14];
    const float* b1 = (const float*)d_in[15];
    const float* m1 = (const float*)d_in[16];
    const float* v1 = (const float*)d_in[17];
    float* out = (float*)d_out;

    const int KNN_SMEM = (NN*68 + NN)*4;              // 141312 B
    const int PQ_SMEM  = (8192 + 8192 + 128 + 64)*4;  // 65792 B
    cudaFuncSetAttribute(k_knn<10>, cudaFuncAttributeMaxDynamicSharedMemorySize, KNN_SMEM);
    cudaFuncSetAttribute(k_knn<8>,  cudaFuncAttributeMaxDynamicSharedMemorySize, KNN_SMEM);
    cudaFuncSetAttribute(k_pq,      cudaFuncAttributeMaxDynamicSharedMemorySize, PQ_SMEM);

    k_prep<<<NB, 256>>>(x, w_erase, b_erase, g_erase, be_erase, m_erase, v_erase);
    k_knn<10><<<dim3(NB,3), 192, KNN_SMEM>>>(0);               // knn on x0
    k_pq<<<dim3(NB,4), 256, PQ_SMEM>>>(0, w0, g0, b0, m0, v0); // branch0 Pt/Qt
    k_gmax<<<dim3(NB,4), 256>>>();                             // partials
    k_fin<<<NB, 128>>>(out, 0);                                // p0 -> out (x0_vec)
    k_knn<8><<<dim3(NB,3), 192, KNN_SMEM>>>(1);                // knn on x1seq
    k_corre<<<NB, 512>>>(w_reduce, out);                       // masks, f
    k_erase1<<<NB, 512>>>(w_erase, b_erase, g_erase, be_erase, m_erase, v_erase);
    k_knn<10><<<dim3(NB,3), 192, KNN_SMEM>>>(2);               // knn on x1e
    k_pq<<<dim3(NB,4), 256, PQ_SMEM>>>(2, w1, g1, b1, m1, v1); // branch1 Pt/Qt
    k_gmax<<<dim3(NB,4), 256>>>();
    k_fin<<<NB, 128>>>(out, 1);                                // out += p1
}

// round 6
// speedup vs baseline: 1.5052x; 1.2294x over previous
#include <cuda_runtime.h>
#include <math.h>

#define NB 96
#define NC 64
#define NN 512
#define NO 64

typedef unsigned long long ull;

// ---------------- scratch (device globals; no allocation) ----------------
__device__ float g_x0 [NB*NC*NN];
__device__ float g_x1 [NB*NC*NN];
__device__ float g_x1e[NB*NC*NN];
__device__ float g_PQ [NB*2*NO*NN];   // per batch: Pt[512][64] then Qt[512][64]
__device__ int   g_i10[NB*NN*10];
__device__ int   g_i8 [NB*NN*8];
__device__ float g_f  [NB*NN];
__device__ float g_msk[NB*NN];
__device__ float g_part[NB*4*128];    // per (b, jq): 0..63 max, 64..127 sum

// ---------------- f32x2 helpers (SASS FFMA2 — PTX-only) ----------------
__device__ __forceinline__ void fma2(ull& acc, ull a, ull b) {
    asm("fma.rn.f32x2 %0, %1, %2, %0;" : "+l"(acc) : "l"(a), "l"(b));
}
__device__ __forceinline__ ull pk2(float lo, float hi) {
    ull r;
    asm("mov.b64 %0, {%1, %2};" : "=l"(r) : "f"(lo), "f"(hi));
    return r;
}
__device__ __forceinline__ float2 upk(ull v) {
    float2 r;
    asm("mov.b64 {%0, %1}, %2;" : "=f"(r.x), "=f"(r.y) : "l"(v));
    return r;
}

// ---------------- kernel 1: erase0 (x -> x0) + temporal shift (x -> x1seq) ----------------
__global__ __launch_bounds__(256) void k_prep(const float* __restrict__ x,
    const float* __restrict__ w_e, const float* __restrict__ b_e,
    const float* __restrict__ g_e, const float* __restrict__ be_e,
    const float* __restrict__ m_e, const float* __restrict__ v_e)
{
    int b = blockIdx.x, tid = threadIdx.x;
    __shared__ float res[NC];
    __shared__ float yb[NC];
    const float* xb = x + (size_t)b*NC*NN;

    int ch = tid >> 2, lane = tid & 3;
    float s = 0.f;
    for (int i = lane; i < NN; i += 4) s += xb[ch*NN + i];
    s += __shfl_down_sync(0xffffffffu, s, 1, 4);
    s += __shfl_down_sync(0xffffffffu, s, 2, 4);
    if (lane == 0) res[ch] = s * (1.0f/NN);
    __syncthreads();

    if (tid < NC) {
        float y = b_e[tid];
        for (int c = 0; c < NC; c++) y = fmaf(w_e[tid*NC + c], res[c], y);
        float sc = g_e[tid] * rsqrtf(v_e[tid] + 1e-5f);
        yb[tid] = (y - m_e[tid]) * sc + be_e[tid];
    }
    __syncthreads();

    int ti = b % 12;
    int tshift = (ti + 1 < 11) ? (ti + 1) : 11;
    int srcb = b - ti + tshift;
    const float* xsft = x + (size_t)srcb*NC*NN;
    float* x0 = g_x0 + (size_t)b*NC*NN;
    float* x1 = g_x1 + (size_t)b*NC*NN;
    for (int idx = tid; idx < NC*NN; idx += 256) {
        int c = idx >> 9;
        x0[idx] = xb[idx] + yb[c];
        x1[idx] = xsft[idx];
    }
}

// ---------------- kNN body: 512 threads, one row each, j-unroll x2 ----------------
template<int K>
__device__ __forceinline__ void knn_body(const float* __restrict__ xb,
                                         int* __restrict__ idxout_b,
                                         float* xs, float* xx)
{
    int tid = threadIdx.x;

    // load all 512 points (one row per thread), channel-major source: coalesced
    {
        int r = tid;
        float acc = 0.f;
        #pragma unroll 8
        for (int cp = 0; cp < NC; cp++) {
            float v = xb[cp*NN + r];
            xs[r*68 + cp] = v;
            acc = fmaf(v, v, acc);
        }
        xx[r] = acc;
    }
    __syncthreads();

    int i = tid;
    ull xiu[32];
    {
        const ulonglong2* xr = (const ulonglong2*)(xs + i*68);
        #pragma unroll
        for (int m = 0; m < 16; m++) {
            ulonglong2 t = xr[m];
            xiu[2*m]   = t.x;
            xiu[2*m+1] = t.y;
        }
    }
    float xxi = xx[i];

    float bv[K]; int bix[K];
    #pragma unroll
    for (int q = 0; q < K; q++) { bv[q] = -3e38f; bix[q] = 0; }

    for (int j = 0; j < NN; j += 2) {
        const ulonglong2* yr0 = (const ulonglong2*)(xs + j*68);       // warp-uniform
        const ulonglong2* yr1 = (const ulonglong2*)(xs + (j+1)*68);   // broadcasts
        ull a0 = 0ull, a1 = 0ull, c0 = 0ull, c1 = 0ull;
        #pragma unroll
        for (int m = 0; m < 16; m++) {
            ulonglong2 y0 = yr0[m];
            ulonglong2 y1 = yr1[m];
            fma2(a0, xiu[2*m],   y0.x);
            fma2(a1, xiu[2*m+1], y0.y);
            fma2(c0, xiu[2*m],   y1.x);
            fma2(c1, xiu[2*m+1], y1.y);
        }
        float2 fa0 = upk(a0), fa1 = upk(a1), fc0 = upk(c0), fc1 = upk(c1);
        float pd0 = 2.0f*((fa0.x+fa0.y)+(fa1.x+fa1.y)) - xxi - xx[j];
        float pd1 = 2.0f*((fc0.x+fc0.y)+(fc1.x+fc1.y)) - xxi - xx[j+1];
        float thr = bv[K-1];
        if (pd0 > thr || pd1 > thr) {          // one divergence region per j-pair
            if (pd0 > bv[K-1]) {
                float v = pd0; int id = j;
                #pragma unroll
                for (int q = 0; q < K; q++) {
                    if (v > bv[q]) {
                        float tv = bv[q]; int tq = bix[q];
                        bv[q] = v; bix[q] = id;
                        v = tv;  id = tq;
                    }
                }
            }
            if (pd1 > bv[K-1]) {
                float v = pd1; int id = j + 1;
                #pragma unroll
                for (int q = 0; q < K; q++) {
                    if (v > bv[q]) {
                        float tv = bv[q]; int tq = bix[q];
                        bv[q] = v; bix[q] = id;
                        v = tv;  id = tq;
                    }
                }
            }
        }
    }
    int* op = idxout_b + (size_t)i*K;
    #pragma unroll
    for (int q = 0; q < K; q++) op[q] = bix[q];
}

// dual launch: blocks [0,96) do k=10 on x0, blocks [96,192) do k=8 on x1 (independent work)
__global__ __launch_bounds__(512) void k_knn_dual()
{
    extern __shared__ float smk[];
    int b = blockIdx.x;
    if (b < NB) {
        knn_body<10>(g_x0 + (size_t)b*NC*NN, g_i10 + (size_t)b*NN*10, smk, smk + NN*68);
    } else {
        b -= NB;
        knn_body<8>(g_x1 + (size_t)b*NC*NN, g_i8 + (size_t)b*NN*8, smk, smk + NN*68);
    }
}

__global__ __launch_bounds__(512) void k_knn_x1e()
{
    extern __shared__ float smk[];
    int b = blockIdx.x;
    knn_body<10>(g_x1e + (size_t)b*NC*NN, g_i10 + (size_t)b*NN*10, smk, smk + NN*68);
}

// ---------------- kernel 3: P'/Q' GEMM (BN folded), FFMA2, TRANSPOSED output ----------------
__global__ __launch_bounds__(256) void k_pq(int sel,
    const float* __restrict__ w, const float* __restrict__ gg,
    const float* __restrict__ bb, const float* __restrict__ mm,
    const float* __restrict__ vv)
{
    extern __shared__ float smp[];
    float* xs2   = smp;            // [64][128] x tile
    float* W2    = smp + 8192;     // [128][64] fused weights
    float* bias2 = smp + 16384;    // [128]
    float* sarr  = bias2 + 128;    // [64]
    const float* xin = (sel == 0) ? g_x0 : g_x1e;

    int b = blockIdx.x, jq = blockIdx.y, tid = threadIdx.x;
    if (tid < 64) sarr[tid] = gg[tid] * rsqrtf(vv[tid] + 1e-5f);
    __syncthreads();

    for (int idx = tid; idx < 128*64; idx += 256) {
        int r = idx >> 6, c = idx & 63;
        float val;
        if (r < 64) val = sarr[r] * w[r*128 + c];
        else { int o = r - 64; val = sarr[o] * (w[o*128 + 64 + c] - w[o*128 + c]); }
        W2[idx] = val;
    }
    if (tid < 128)
        bias2[tid] = (tid < 64) ? 0.f : (bb[tid-64] - mm[tid-64]*sarr[tid-64]);

    const float* xb = xin + (size_t)b*NC*NN + jq*128;
    for (int idx = tid; idx < 64*128; idx += 256) {
        int c = idx >> 7, jj = idx & 127;
        xs2[idx] = xb[c*NN + jj];
    }
    __syncthreads();

    int rt = tid >> 4, ct = tid & 15;
    int r0 = rt*8, j0 = ct*8;
    ull accp[8][4];
    #pragma unroll
    for (int u = 0; u < 8; u++)
        #pragma unroll
        for (int vp = 0; vp < 4; vp++) accp[u][vp] = 0ull;

    for (int kk = 0; kk < 64; kk++) {
        ull wp[8];
        #pragma unroll
        for (int u = 0; u < 8; u++) {
            float wv = W2[(r0+u)*64 + kk];
            wp[u] = pk2(wv, wv);
        }
        const ulonglong2* xp = (const ulonglong2*)(xs2 + kk*128 + j0);
        ulonglong2 xa = xp[0], xc = xp[1];
        #pragma unroll
        for (int u = 0; u < 8; u++) {
            fma2(accp[u][0], wp[u], xa.x);
            fma2(accp[u][1], wp[u], xa.y);
            fma2(accp[u][2], wp[u], xc.x);
            fma2(accp[u][3], wp[u], xc.y);
        }
    }

    float a[8][8];
    #pragma unroll
    for (int u = 0; u < 8; u++) {
        float bsv = bias2[r0+u];
        #pragma unroll
        for (int vp = 0; vp < 4; vp++) {
            float2 t = upk(accp[u][vp]);
            a[u][2*vp]   = t.x + bsv;
            a[u][2*vp+1] = t.y + bsv;
        }
    }

    float* Ptb = g_PQ + (size_t)b*2*NO*NN;      // [512][64]
    float* Qtb = Ptb + (size_t)NN*NO;           // [512][64]
    #pragma unroll
    for (int v = 0; v < 8; v++) {
        int j = jq*128 + j0 + v;
        float* dst = (r0 < 64) ? (Ptb + (size_t)j*64 + r0)
                               : (Qtb + (size_t)j*64 + (r0-64));
        float4 o0 = make_float4(a[0][v], a[1][v], a[2][v], a[3][v]);
        float4 o1 = make_float4(a[4][v], a[5][v], a[6][v], a[7][v]);
        *(float4*)(dst)     = o0;
        *(float4*)(dst + 4) = o1;
    }
}

// ---------------- kernel 4: gather-max over k + lrelu + partial max/mean ----------------
__global__ __launch_bounds__(256) void k_gmax()
{
    int b = blockIdx.x, jq = blockIdx.y, tid = threadIdx.x;
    int w = tid >> 5, l = tid & 31;
    const float* Pt = g_PQ + (size_t)b*2*NO*NN;
    const float* Qt = Pt + (size_t)NN*NO;
    const int* ig = g_i10 + (size_t)b*NN*10;

    float mx0 = -3e38f, mx1 = -3e38f, s0 = 0.f, s1 = 0.f;
    #pragma unroll 2
    for (int p = 0; p < 16; p++) {
        int i = jq*128 + w*16 + p;
        const int* ip = ig + (size_t)i*10;
        float a0 = -3e38f, a1 = -3e38f;
        #pragma unroll
        for (int kk = 0; kk < 10; kk++) {
            int nb = ip[kk];                               // uniform -> broadcast
            float2 pv = *(const float2*)(Pt + (size_t)nb*64 + 2*l);
            a0 = fmaxf(a0, pv.x);
            a1 = fmaxf(a1, pv.y);
        }
        float2 q = *(const float2*)(Qt + (size_t)i*64 + 2*l);
        float y0 = a0 + q.x; y0 = (y0 > 0.f) ? y0 : 0.2f*y0;
        float y1 = a1 + q.y; y1 = (y1 > 0.f) ? y1 : 0.2f*y1;
        mx0 = fmaxf(mx0, y0); s0 += y0;
        mx1 = fmaxf(mx1, y1); s1 += y1;
    }

    __shared__ float sred[8][128];
    sred[w][2*l]      = mx0;
    sred[w][2*l+1]    = mx1;
    sred[w][64+2*l]   = s0;
    sred[w][64+2*l+1] = s1;
    __syncthreads();
    if (tid < 128) {
        float v;
        if (tid < 64) {
            v = sred[0][tid];
            #pragma unroll
            for (int ww = 1; ww < 8; ww++) v = fmaxf(v, sred[ww][tid]);
        } else {
            v = sred[0][tid];
            #pragma unroll
            for (int ww = 1; ww < 8; ww++) v += sred[ww][tid];
        }
        g_part[((size_t)b*4 + jq)*128 + tid] = v;
    }
}

// ---------------- kernel 4b: final reduction over the 4 point-chunks ----------------
__global__ __launch_bounds__(128) void k_fin(float* __restrict__ out, int accumulate)
{
    int b = blockIdx.x, tid = threadIdx.x;
    const float* pp = g_part + (size_t)b*4*128;
    float v;
    if (tid < 64) {
        v = pp[tid];
        #pragma unroll
        for (int jq = 1; jq < 4; jq++) v = fmaxf(v, pp[jq*128 + tid]);
    } else {
        v = pp[tid];
        #pragma unroll
        for (int jq = 1; jq < 4; jq++) v += pp[jq*128 + tid];
        v *= (1.0f/NN);
    }
    if (accumulate) out[b*128 + tid] += v;
    else            out[b*128 + tid]  = v;
}

// ---------------- kernel 5: corre_binar (q, f, fk, argmax, masks) ----------------
__global__ __launch_bounds__(512) void k_corre(const float* __restrict__ w_red,
                                               const float* __restrict__ outv)
{
    __shared__ float qv[64];
    __shared__ float fs[NN];
    __shared__ float rv[NN];
    __shared__ int   ri[NN];
    int b = blockIdx.x, tid = threadIdx.x;
    if (tid < 64) {
        const float* xv = outv + b*128;    // x0_vec == p0 max-half
        float a = 0.f;
        for (int c = 0; c < 64; c++) a = fmaf(w_red[tid*64 + c], xv[c], a);
        qv[tid] = a;
    }
    __syncthreads();
    const float* x1b = g_x1 + (size_t)b*NC*NN;
    float f = 0.f;
    for (int c = 0; c < 64; c++) f = fmaf(qv[c], x1b[c*NN + tid], f);
    f *= 0.125f;
    fs[tid] = f;
    g_f[b*NN + tid] = f;
    __syncthreads();
    const int* i8 = g_i8 + ((size_t)b*NN + tid)*8;
    float fk = f;
    #pragma unroll
    for (int kk = 0; kk < 8; kk++) fk += fs[i8[kk]];
    rv[tid] = fk; ri[tid] = tid;
    __syncthreads();
    for (int s2 = 256; s2 > 0; s2 >>= 1) {   // argmax, ties -> lowest index
        if (tid < s2) {
            float a = rv[tid], b2 = rv[tid + s2];
            int ia = ri[tid], ib2 = ri[tid + s2];
            if (b2 > a || (b2 == a && ib2 < ia)) { rv[tid] = b2; ri[tid] = ib2; }
        }
        __syncthreads();
    }
    int widx = ri[0];
    g_msk[b*NN + tid] = 1.0f;
    __syncthreads();
    if (tid == 0) g_msk[b*NN + widx] = 0.f;
    if (tid < 8)  g_msk[b*NN + g_i8[((size_t)b*NN + widx)*8 + tid]] = 0.f;
}

// ---------------- kernel 6: erase1 (masked softmax attention + conv_erase) ----------------
__global__ __launch_bounds__(512) void k_erase1(
    const float* __restrict__ w_e, const float* __restrict__ b_e,
    const float* __restrict__ g_e, const float* __restrict__ be_e,
    const float* __restrict__ m_e, const float* __restrict__ v_e)
{
    __shared__ float smw[NN];
    __shared__ float red[NN];
    __shared__ float msk[NN];
    __shared__ float res[64];
    __shared__ float yb[64];
    int b = blockIdx.x, tid = threadIdx.x;
    const float* x1b = g_x1 + (size_t)b*NC*NN;

    float M = g_msk[b*NN + tid];
    float f = g_f[b*NN + tid];
    msk[tid] = M;
    float z = f - (1.0f - M)*1e8f;
    red[tid] = z;
    __syncthreads();
    for (int s2 = 256; s2 > 0; s2 >>= 1) {
        if (tid < s2) red[tid] = fmaxf(red[tid], red[tid + s2]);
        __syncthreads();
    }
    float zmax = red[0];
    __syncthreads();
    float e = expf(z - zmax);
    red[tid] = e;
    __syncthreads();
    for (int s2 = 256; s2 > 0; s2 >>= 1) {
        if (tid < s2) red[tid] += red[tid + s2];
        __syncthreads();
    }
    float esum = red[0];
    smw[tid] = e / esum;
    __syncthreads();

    int ch = tid >> 3, ln = tid & 7;
    float a = 0.f;
    for (int i = ln; i < NN; i += 8) a = fmaf(x1b[ch*NN + i], smw[i], a);
    a += __shfl_down_sync(0xffffffffu, a, 1, 8);
    a += __shfl_down_sync(0xffffffffu, a, 2, 8);
    a += __shfl_down_sync(0xffffffffu, a, 4, 8);
    if (ln == 0) res[ch] = a;
    __syncthreads();

    if (tid < 64) {
        float y = b_e[tid];
        for (int c = 0; c < 64; c++) y = fmaf(w_e[tid*64 + c], res[c], y);
        float sc = g_e[tid]*rsqrtf(v_e[tid] + 1e-5f);
        yb[tid] = (y - m_e[tid])*sc + be_e[tid];
    }
    __syncthreads();

    float* xo = g_x1e + (size_t)b*NC*NN;
    for (int idx = tid; idx < NC*NN; idx += 512) {
        int c = idx >> 9, i = idx & 511;
        xo[idx] = x1b[idx]*msk[i] + yb[c];
    }
}

// ---------------- launcher ----------------
extern "C" void kernel_launch(void* const* d_in, const int* in_sizes, int n_in,
                              void* d_out, int out_size)
{
    const float* x        = (const float*)d_in[0];
    const float* w_reduce = (const float*)d_in[1];
    const float* w_erase  = (const float*)d_in[2];
    const float* b_erase  = (const float*)d_in[3];
    const float* g_erase  = (const float*)d_in[4];
    const float* be_erase = (const float*)d_in[5];
    const float* m_erase  = (const float*)d_in[6];
    const float* v_erase  = (const float*)d_in[7];
    const float* w0 = (const float*)d_in[8];
    const float* g0 = (const float*)d_in[9];
    const float* b0 = (const float*)d_in[10];
    const float* m0 = (const float*)d_in[11];
    const float* v0 = (const float*)d_in[12];
    const float* w1 = (const float*)d_in[13];
    const float* g1 = (const float*)d_in[14];
    const float* b1 = (const float*)d_in[15];
    const float* m1 = (const float*)d_in[16];
    const float* v1 = (const float*)d_in[17];
    float* out = (float*)d_out;

    const int KNN_SMEM = (NN*68 + NN)*4;              // 141312 B
    const int PQ_SMEM  = (8192 + 8192 + 128 + 64)*4;  // 65792 B
    cudaFuncSetAttribute(k_knn_dual, cudaFuncAttributeMaxDynamicSharedMemorySize, KNN_SMEM);
    cudaFuncSetAttribute(k_knn_x1e,  cudaFuncAttributeMaxDynamicSharedMemorySize, KNN_SMEM);
    cudaFuncSetAttribute(k_pq,       cudaFuncAttributeMaxDynamicSharedMemorySize, PQ_SMEM);

    k_prep<<<NB, 256>>>(x, w_erase, b_erase, g_erase, be_erase, m_erase, v_erase);
    k_knn_dual<<<2*NB, 512, KNN_SMEM>>>();                     // knn10(x0) + knn8(x1) fused
    k_pq<<<dim3(NB,4), 256, PQ_SMEM>>>(0, w0, g0, b0, m0, v0); // branch0 Pt/Qt
    k_gmax<<<dim3(NB,4), 256>>>();                             // partials
    k_fin<<<NB, 128>>>(out, 0);                                // p0 -> out (x0_vec)
    k_corre<<<NB, 512>>>(w_reduce, out);                       // masks, f
    k_erase1<<<NB, 512>>>(w_erase, b_erase, g_erase, be_erase, m_erase, v_erase);
    k_knn_x1e<<<NB, 512, KNN_SMEM>>>();                        // knn10 on x1e
    k_pq<<<dim3(NB,4), 256, PQ_SMEM>>>(2, w1, g1, b1, m1, v1); // branch1 Pt/Qt
    k_gmax<<<dim3(NB,4), 256>>>();
    k_fin<<<NB, 128>>>(out, 1);                                // out += p1
}

// round 7
// speedup vs baseline: 1.6382x; 1.0884x over previous
#include <cuda_runtime.h>
#include <math.h>

#define NB 96
#define NC 64
#define NN 512
#define NO 64

typedef unsigned long long ull;

// ---------------- scratch (device globals; no allocation) ----------------
__device__ float g_x0 [NB*NC*NN];
__device__ float g_x1 [NB*NC*NN];
__device__ float g_x1e[NB*NC*NN];
__device__ float g_PQ [NB*2*NO*NN];   // per batch: Pt[512][64] then Qt[512][64]
__device__ int   g_i10[NB*NN*10];
__device__ int   g_i8 [NB*NN*8];
__device__ float g_f  [NB*NN];
__device__ float g_msk[NB*NN];
__device__ float g_part[NB*4*128];    // per (b, jq): 0..63 max, 64..127 sum
// partial top-k candidates: [b][js][i][K]
__device__ float g_c10v[NB*3*NN*10];
__device__ int   g_c10i[NB*3*NN*10];
__device__ float g_c8v [NB*3*NN*8];
__device__ int   g_c8i [NB*3*NN*8];

// ---------------- f32x2 helpers (SASS FFMA2 — PTX-only) ----------------
__device__ __forceinline__ void fma2(ull& acc, ull a, ull b) {
    asm("fma.rn.f32x2 %0, %1, %2, %0;" : "+l"(acc) : "l"(a), "l"(b));
}
__device__ __forceinline__ ull pk2(float lo, float hi) {
    ull r;
    asm("mov.b64 %0, {%1, %2};" : "=l"(r) : "f"(lo), "f"(hi));
    return r;
}
__device__ __forceinline__ float2 upk(ull v) {
    float2 r;
    asm("mov.b64 {%0, %1}, %2;" : "=f"(r.x), "=f"(r.y) : "l"(v));
    return r;
}

// ---------------- kernel 1: erase0 (x -> x0) + temporal shift (x -> x1seq) ----------------
__global__ __launch_bounds__(256) void k_prep(const float* __restrict__ x,
    const float* __restrict__ w_e, const float* __restrict__ b_e,
    const float* __restrict__ g_e, const float* __restrict__ be_e,
    const float* __restrict__ m_e, const float* __restrict__ v_e)
{
    int b = blockIdx.x, tid = threadIdx.x;
    __shared__ float res[NC];
    __shared__ float yb[NC];
    const float* xb = x + (size_t)b*NC*NN;

    int ch = tid >> 2, lane = tid & 3;
    float s = 0.f;
    for (int i = lane; i < NN; i += 4) s += xb[ch*NN + i];
    s += __shfl_down_sync(0xffffffffu, s, 1, 4);
    s += __shfl_down_sync(0xffffffffu, s, 2, 4);
    if (lane == 0) res[ch] = s * (1.0f/NN);
    __syncthreads();

    if (tid < NC) {
        float y = b_e[tid];
        for (int c = 0; c < NC; c++) y = fmaf(w_e[tid*NC + c], res[c], y);
        float sc = g_e[tid] * rsqrtf(v_e[tid] + 1e-5f);
        yb[tid] = (y - m_e[tid]) * sc + be_e[tid];
    }
    __syncthreads();

    int ti = b % 12;
    int tshift = (ti + 1 < 11) ? (ti + 1) : 11;
    int srcb = b - ti + tshift;
    const float* xsft = x + (size_t)srcb*NC*NN;
    float* x0 = g_x0 + (size_t)b*NC*NN;
    float* x1 = g_x1 + (size_t)b*NC*NN;
    for (int idx = tid; idx < NC*NN; idx += 256) {
        int c = idx >> 9;
        x0[idx] = xb[idx] + yb[c];
        x1[idx] = xsft[idx];
    }
}

// ---------------- kNN partial: 512 threads, one query row each, j-subrange ----------------
// j ranges (even, for x2 unroll): js=0 -> [0,172), js=1 -> [172,344), js=2 -> [344,512)
template<int K>
__device__ __forceinline__ void knn_part(const float* __restrict__ xb,
                                         float* __restrict__ cv,   // [NN][K] this slice
                                         int*   __restrict__ ci,
                                         int jlo, int jhi,
                                         float* xs, float* xx)
{
    int tid = threadIdx.x;

    // load all 512 points (one row per thread), channel-major source: coalesced
    {
        int r = tid;
        float acc = 0.f;
        #pragma unroll 8
        for (int cp = 0; cp < NC; cp++) {
            float v = xb[cp*NN + r];
            xs[r*68 + cp] = v;
            acc = fmaf(v, v, acc);
        }
        xx[r] = acc;
    }
    __syncthreads();

    int i = tid;
    ull xiu[32];
    {
        const ulonglong2* xr = (const ulonglong2*)(xs + i*68);
        #pragma unroll
        for (int m = 0; m < 16; m++) {
            ulonglong2 t = xr[m];
            xiu[2*m]   = t.x;
            xiu[2*m+1] = t.y;
        }
    }
    float xxi = xx[i];

    float bv[K]; int bix[K];
    #pragma unroll
    for (int q = 0; q < K; q++) { bv[q] = -3e38f; bix[q] = 0; }

    for (int j = jlo; j < jhi; j += 2) {
        const ulonglong2* yr0 = (const ulonglong2*)(xs + j*68);       // warp-uniform
        const ulonglong2* yr1 = (const ulonglong2*)(xs + (j+1)*68);   // broadcasts
        ull a0 = 0ull, a1 = 0ull, c0 = 0ull, c1 = 0ull;
        #pragma unroll
        for (int m = 0; m < 16; m++) {
            ulonglong2 y0 = yr0[m];
            ulonglong2 y1 = yr1[m];
            fma2(a0, xiu[2*m],   y0.x);
            fma2(a1, xiu[2*m+1], y0.y);
            fma2(c0, xiu[2*m],   y1.x);
            fma2(c1, xiu[2*m+1], y1.y);
        }
        float2 fa0 = upk(a0), fa1 = upk(a1), fc0 = upk(c0), fc1 = upk(c1);
        float pd0 = 2.0f*((fa0.x+fa0.y)+(fa1.x+fa1.y)) - xxi - xx[j];
        float pd1 = 2.0f*((fc0.x+fc0.y)+(fc1.x+fc1.y)) - xxi - xx[j+1];
        float thr = bv[K-1];
        if (pd0 > thr || pd1 > thr) {          // one divergence region per j-pair
            if (pd0 > bv[K-1]) {
                float v = pd0; int id = j;
                #pragma unroll
                for (int q = 0; q < K; q++) {
                    if (v > bv[q]) {
                        float tv = bv[q]; int tq = bix[q];
                        bv[q] = v; bix[q] = id;
                        v = tv;  id = tq;
                    }
                }
            }
            if (pd1 > bv[K-1]) {
                float v = pd1; int id = j + 1;
                #pragma unroll
                for (int q = 0; q < K; q++) {
                    if (v > bv[q]) {
                        float tv = bv[q]; int tq = bix[q];
                        bv[q] = v; bix[q] = id;
                        v = tv;  id = tq;
                    }
                }
            }
        }
    }
    float* ov = cv + (size_t)i*K;
    int*   oi = ci + (size_t)i*K;
    #pragma unroll
    for (int q = 0; q < K; q++) { ov[q] = bv[q]; oi[q] = bix[q]; }
}

__device__ __forceinline__ void jrange(int js, int& jlo, int& jhi) {
    jlo = (js == 0) ? 0 : (js == 1 ? 172 : 344);
    jhi = (js == 0) ? 172 : (js == 1 ? 344 : 512);
}

// dual: blocks [0,288) = k10 on x0 (96 tasks x 3 slices); [288,576) = k8 on x1
__global__ __launch_bounds__(512) void k_knn_dual()
{
    extern __shared__ float smk[];
    int bb = blockIdx.x;
    int jlo, jhi;
    if (bb < 3*NB) {
        int b = bb / 3, js = bb % 3;
        jrange(js, jlo, jhi);
        knn_part<10>(g_x0 + (size_t)b*NC*NN,
                     g_c10v + ((size_t)b*3 + js)*NN*10,
                     g_c10i + ((size_t)b*3 + js)*NN*10,
                     jlo, jhi, smk, smk + NN*68);
    } else {
        bb -= 3*NB;
        int b = bb / 3, js = bb % 3;
        jrange(js, jlo, jhi);
        knn_part<8>(g_x1 + (size_t)b*NC*NN,
                    g_c8v + ((size_t)b*3 + js)*NN*8,
                    g_c8i + ((size_t)b*3 + js)*NN*8,
                    jlo, jhi, smk, smk + NN*68);
    }
}

__global__ __launch_bounds__(512) void k_knn_x1e()
{
    extern __shared__ float smk[];
    int b = blockIdx.x / 3, js = blockIdx.x % 3;
    int jlo, jhi;
    jrange(js, jlo, jhi);
    knn_part<10>(g_x1e + (size_t)b*NC*NN,
                 g_c10v + ((size_t)b*3 + js)*NN*10,
                 g_c10i + ((size_t)b*3 + js)*NN*10,
                 jlo, jhi, smk, smk + NN*68);
}

// ---------------- merge 3 partial sorted top-K lists -> final indices ----------------
// Stable: lists processed in ascending j-range order; strict-> insert keeps
// earlier (lower-index) entries ahead on value ties, matching lax.top_k order.
template<int K>
__device__ __forceinline__ void merge_body(const float* __restrict__ cv,
                                           const int* __restrict__ ci,
                                           int* __restrict__ idxout, int b)
{
    int i = threadIdx.x;
    float bv[K]; int bix[K];
    #pragma unroll
    for (int q = 0; q < K; q++) { bv[q] = -3e38f; bix[q] = 0; }
    for (int js = 0; js < 3; js++) {
        const float* v = cv + (((size_t)b*3 + js)*NN + i)*K;
        const int*   d = ci + (((size_t)b*3 + js)*NN + i)*K;
        #pragma unroll
        for (int q0 = 0; q0 < K; q0++) {
            float val = v[q0]; int id = d[q0];
            if (val > bv[K-1]) {
                #pragma unroll
                for (int q = 0; q < K; q++) {
                    if (val > bv[q]) {
                        float tv = bv[q]; int tq = bix[q];
                        bv[q] = val; bix[q] = id;
                        val = tv; id = tq;
                    }
                }
            }
        }
    }
    int* op = idxout + ((size_t)b*NN + i)*K;
    #pragma unroll
    for (int q = 0; q < K; q++) op[q] = bix[q];
}

// grid 192: [0,96) merge k10 -> g_i10, [96,192) merge k8 -> g_i8
__global__ __launch_bounds__(512) void k_merge_dual()
{
    int b = blockIdx.x;
    if (b < NB) merge_body<10>(g_c10v, g_c10i, g_i10, b);
    else        merge_body<8>(g_c8v, g_c8i, g_i8, b - NB);
}

__global__ __launch_bounds__(512) void k_merge_x1e()
{
    merge_body<10>(g_c10v, g_c10i, g_i10, blockIdx.x);
}

// ---------------- kernel 3: P'/Q' GEMM (BN folded), FFMA2, TRANSPOSED output ----------------
__global__ __launch_bounds__(256) void k_pq(int sel,
    const float* __restrict__ w, const float* __restrict__ gg,
    const float* __restrict__ bb, const float* __restrict__ mm,
    const float* __restrict__ vv)
{
    extern __shared__ float smp[];
    float* xs2   = smp;            // [64][128] x tile
    float* W2    = smp + 8192;     // [128][64] fused weights
    float* bias2 = smp + 16384;    // [128]
    float* sarr  = bias2 + 128;    // [64]
    const float* xin = (sel == 0) ? g_x0 : g_x1e;

    int b = blockIdx.x, jq = blockIdx.y, tid = threadIdx.x;
    if (tid < 64) sarr[tid] = gg[tid] * rsqrtf(vv[tid] + 1e-5f);
    __syncthreads();

    for (int idx = tid; idx < 128*64; idx += 256) {
        int r = idx >> 6, c = idx & 63;
        float val;
        if (r < 64) val = sarr[r] * w[r*128 + c];
        else { int o = r - 64; val = sarr[o] * (w[o*128 + 64 + c] - w[o*128 + c]); }
        W2[idx] = val;
    }
    if (tid < 128)
        bias2[tid] = (tid < 64) ? 0.f : (bb[tid-64] - mm[tid-64]*sarr[tid-64]);

    const float* xb = xin + (size_t)b*NC*NN + jq*128;
    for (int idx = tid; idx < 64*128; idx += 256) {
        int c = idx >> 7, jj = idx & 127;
        xs2[idx] = xb[c*NN + jj];
    }
    __syncthreads();

    int rt = tid >> 4, ct = tid & 15;
    int r0 = rt*8, j0 = ct*8;
    ull accp[8][4];
    #pragma unroll
    for (int u = 0; u < 8; u++)
        #pragma unroll
        for (int vp = 0; vp < 4; vp++) accp[u][vp] = 0ull;

    for (int kk = 0; kk < 64; kk++) {
        ull wp[8];
        #pragma unroll
        for (int u = 0; u < 8; u++) {
            float wv = W2[(r0+u)*64 + kk];
            wp[u] = pk2(wv, wv);
        }
        const ulonglong2* xp = (const ulonglong2*)(xs2 + kk*128 + j0);
        ulonglong2 xa = xp[0], xc = xp[1];
        #pragma unroll
        for (int u = 0; u < 8; u++) {
            fma2(accp[u][0], wp[u], xa.x);
            fma2(accp[u][1], wp[u], xa.y);
            fma2(accp[u][2], wp[u], xc.x);
            fma2(accp[u][3], wp[u], xc.y);
        }
    }

    float a[8][8];
    #pragma unroll
    for (int u = 0; u < 8; u++) {
        float bsv = bias2[r0+u];
        #pragma unroll
        for (int vp = 0; vp < 4; vp++) {
            float2 t = upk(accp[u][vp]);
            a[u][2*vp]   = t.x + bsv;
            a[u][2*vp+1] = t.y + bsv;
        }
    }

    float* Ptb = g_PQ + (size_t)b*2*NO*NN;      // [512][64]
    float* Qtb = Ptb + (size_t)NN*NO;           // [512][64]
    #pragma unroll
    for (int v = 0; v < 8; v++) {
        int j = jq*128 + j0 + v;
        float* dst = (r0 < 64) ? (Ptb + (size_t)j*64 + r0)
                               : (Qtb + (size_t)j*64 + (r0-64));
        float4 o0 = make_float4(a[0][v], a[1][v], a[2][v], a[3][v]);
        float4 o1 = make_float4(a[4][v], a[5][v], a[6][v], a[7][v]);
        *(float4*)(dst)     = o0;
        *(float4*)(dst + 4) = o1;
    }
}

// ---------------- kernel 4: gather-max over k + lrelu + partial max/mean ----------------
__global__ __launch_bounds__(256) void k_gmax()
{
    int b = blockIdx.x, jq = blockIdx.y, tid = threadIdx.x;
    int w = tid >> 5, l = tid & 31;
    const float* Pt = g_PQ + (size_t)b*2*NO*NN;
    const float* Qt = Pt + (size_t)NN*NO;
    const int* ig = g_i10 + (size_t)b*NN*10;

    float mx0 = -3e38f, mx1 = -3e38f, s0 = 0.f, s1 = 0.f;
    #pragma unroll 2
    for (int p = 0; p < 16; p++) {
        int i = jq*128 + w*16 + p;
        const int* ip = ig + (size_t)i*10;
        float a0 = -3e38f, a1 = -3e38f;
        #pragma unroll
        for (int kk = 0; kk < 10; kk++) {
            int nb = ip[kk];                               // uniform -> broadcast
            float2 pv = *(const float2*)(Pt + (size_t)nb*64 + 2*l);
            a0 = fmaxf(a0, pv.x);
            a1 = fmaxf(a1, pv.y);
        }
        float2 q = *(const float2*)(Qt + (size_t)i*64 + 2*l);
        float y0 = a0 + q.x; y0 = (y0 > 0.f) ? y0 : 0.2f*y0;
        float y1 = a1 + q.y; y1 = (y1 > 0.f) ? y1 : 0.2f*y1;
        mx0 = fmaxf(mx0, y0); s0 += y0;
        mx1 = fmaxf(mx1, y1); s1 += y1;
    }

    __shared__ float sred[8][128];
    sred[w][2*l]      = mx0;
    sred[w][2*l+1]    = mx1;
    sred[w][64+2*l]   = s0;
    sred[w][64+2*l+1] = s1;
    __syncthreads();
    if (tid < 128) {
        float v;
        if (tid < 64) {
            v = sred[0][tid];
            #pragma unroll
            for (int ww = 1; ww < 8; ww++) v = fmaxf(v, sred[ww][tid]);
        } else {
            v = sred[0][tid];
            #pragma unroll
            for (int ww = 1; ww < 8; ww++) v += sred[ww][tid];
        }
        g_part[((size_t)b*4 + jq)*128 + tid] = v;
    }
}

// ---------------- kernel 4b: final reduction over the 4 point-chunks ----------------
__global__ __launch_bounds__(128) void k_fin(float* __restrict__ out, int accumulate)
{
    int b = blockIdx.x, tid = threadIdx.x;
    const float* pp = g_part + (size_t)b*4*128;
    float v;
    if (tid < 64) {
        v = pp[tid];
        #pragma unroll
        for (int jq = 1; jq < 4; jq++) v = fmaxf(v, pp[jq*128 + tid]);
    } else {
        v = pp[tid];
        #pragma unroll
        for (int jq = 1; jq < 4; jq++) v += pp[jq*128 + tid];
        v *= (1.0f/NN);
    }
    if (accumulate) out[b*128 + tid] += v;
    else            out[b*128 + tid]  = v;
}

// ---------------- kernel 5: corre_binar (q, f, fk, argmax, masks) ----------------
__global__ __launch_bounds__(512) void k_corre(const float* __restrict__ w_red,
                                               const float* __restrict__ outv)
{
    __shared__ float qv[64];
    __shared__ float fs[NN];
    __shared__ float rv[NN];
    __shared__ int   ri[NN];
    int b = blockIdx.x, tid = threadIdx.x;
    if (tid < 64) {
        const float* xv = outv + b*128;    // x0_vec == p0 max-half
        float a = 0.f;
        for (int c = 0; c < 64; c++) a = fmaf(w_red[tid*64 + c], xv[c], a);
        qv[tid] = a;
    }
    __syncthreads();
    const float* x1b = g_x1 + (size_t)b*NC*NN;
    float f = 0.f;
    for (int c = 0; c < 64; c++) f = fmaf(qv[c], x1b[c*NN + tid], f);
    f *= 0.125f;
    fs[tid] = f;
    g_f[b*NN + tid] = f;
    __syncthreads();
    const int* i8 = g_i8 + ((size_t)b*NN + tid)*8;
    float fk = f;
    #pragma unroll
    for (int kk = 0; kk < 8; kk++) fk += fs[i8[kk]];
    rv[tid] = fk; ri[tid] = tid;
    __syncthreads();
    for (int s2 = 256; s2 > 0; s2 >>= 1) {   // argmax, ties -> lowest index
        if (tid < s2) {
            float a = rv[tid], b2 = rv[tid + s2];
            int ia = ri[tid], ib2 = ri[tid + s2];
            if (b2 > a || (b2 == a && ib2 < ia)) { rv[tid] = b2; ri[tid] = ib2; }
        }
        __syncthreads();
    }
    int widx = ri[0];
    g_msk[b*NN + tid] = 1.0f;
    __syncthreads();
    if (tid == 0) g_msk[b*NN + widx] = 0.f;
    if (tid < 8)  g_msk[b*NN + g_i8[((size_t)b*NN + widx)*8 + tid]] = 0.f;
}

// ---------------- kernel 6: erase1 (masked softmax attention + conv_erase) ----------------
__global__ __launch_bounds__(512) void k_erase1(
    const float* __restrict__ w_e, const float* __restrict__ b_e,
    const float* __restrict__ g_e, const float* __restrict__ be_e,
    const float* __restrict__ m_e, const float* __restrict__ v_e)
{
    __shared__ float smw[NN];
    __shared__ float red[NN];
    __shared__ float msk[NN];
    __shared__ float res[64];
    __shared__ float yb[64];
    int b = blockIdx.x, tid = threadIdx.x;
    const float* x1b = g_x1 + (size_t)b*NC*NN;

    float M = g_msk[b*NN + tid];
    float f = g_f[b*NN + tid];
    msk[tid] = M;
    float z = f - (1.0f - M)*1e8f;
    red[tid] = z;
    __syncthreads();
    for (int s2 = 256; s2 > 0; s2 >>= 1) {
        if (tid < s2) red[tid] = fmaxf(red[tid], red[tid + s2]);
        __syncthreads();
    }
    float zmax = red[0];
    __syncthreads();
    float e = expf(z - zmax);
    red[tid] = e;
    __syncthreads();
    for (int s2 = 256; s2 > 0; s2 >>= 1) {
        if (tid < s2) red[tid] += red[tid + s2];
        __syncthreads();
    }
    float esum = red[0];
    smw[tid] = e / esum;
    __syncthreads();

    int ch = tid >> 3, ln = tid & 7;
    float a = 0.f;
    for (int i = ln; i < NN; i += 8) a = fmaf(x1b[ch*NN + i], smw[i], a);
    a += __shfl_down_sync(0xffffffffu, a, 1, 8);
    a += __shfl_down_sync(0xffffffffu, a, 2, 8);
    a += __shfl_down_sync(0xffffffffu, a, 4, 8);
    if (ln == 0) res[ch] = a;
    __syncthreads();

    if (tid < 64) {
        float y = b_e[tid];
        for (int c = 0; c < 64; c++) y = fmaf(w_e[tid*64 + c], res[c], y);
        float sc = g_e[tid]*rsqrtf(v_e[tid] + 1e-5f);
        yb[tid] = (y - m_e[tid])*sc + be_e[tid];
    }
    __syncthreads();

    float* xo = g_x1e + (size_t)b*NC*NN;
    for (int idx = tid; idx < NC*NN; idx += 512) {
        int c = idx >> 9, i = idx & 511;
        xo[idx] = x1b[idx]*msk[i] + yb[c];
    }
}

// ---------------- launcher ----------------
extern "C" void kernel_launch(void* const* d_in, const int* in_sizes, int n_in,
                              void* d_out, int out_size)
{
    const float* x        = (const float*)d_in[0];
    const float* w_reduce = (const float*)d_in[1];
    const float* w_erase  = (const float*)d_in[2];
    const float* b_erase  = (const float*)d_in[3];
    const float* g_erase  = (const float*)d_in[4];
    const float* be_erase = (const float*)d_in[5];
    const float* m_erase  = (const float*)d_in[6];
    const float* v_erase  = (const float*)d_in[7];
    const float* w0 = (const float*)d_in[8];
    const float* g0 = (const float*)d_in[9];
    const float* b0 = (const float*)d_in[10];
    const float* m0 = (const float*)d_in[11];
    const float* v0 = (const float*)d_in[12];
    const float* w1 = (const float*)d_in[13];
    const float* g1 = (const float*)d_in[14];
    const float* b1 = (const float*)d_in[15];
    const float* m1 = (const float*)d_in[16];
    const float* v1 = (const float*)d_in[17];
    float* out = (float*)d_out;

    const int KNN_SMEM = (NN*68 + NN)*4;              // 141312 B
    const int PQ_SMEM  = (8192 + 8192 + 128 + 64)*4;  // 65792 B
    cudaFuncSetAttribute(k_knn_dual, cudaFuncAttributeMaxDynamicSharedMemorySize, KNN_SMEM);
    cudaFuncSetAttribute(k_knn_x1e,  cudaFuncAttributeMaxDynamicSharedMemorySize, KNN_SMEM);
    cudaFuncSetAttribute(k_pq,       cudaFuncAttributeMaxDynamicSharedMemorySize, PQ_SMEM);

    k_prep<<<NB, 256>>>(x, w_erase, b_erase, g_erase, be_erase, m_erase, v_erase);
    k_knn_dual<<<6*NB, 512, KNN_SMEM>>>();                     // partial knn10(x0)+knn8(x1)
    k_merge_dual<<<2*NB, 512>>>();                             // -> g_i10, g_i8
    k_pq<<<dim3(NB,4), 256, PQ_SMEM>>>(0, w0, g0, b0, m0, v0); // branch0 Pt/Qt
    k_gmax<<<dim3(NB,4), 256>>>();                             // partials
    k_fin<<<NB, 128>>>(out, 0);                                // p0 -> out (x0_vec)
    k_corre<<<NB, 512>>>(w_reduce, out);                       // masks, f
    k_erase1<<<NB, 512>>>(w_erase, b_erase, g_erase, be_erase, m_erase, v_erase);
    k_knn_x1e<<<3*NB, 512, KNN_SMEM>>>();                      // partial knn10 on x1e
    k_merge_x1e<<<NB, 512>>>();                                // -> g_i10
    k_pq<<<dim3(NB,4), 256, PQ_SMEM>>>(2, w1, g1, b1, m1, v1); // branch1 Pt/Qt
    k_gmax<<<dim3(NB,4), 256>>>();
    k_fin<<<NB, 128>>>(out, 1);                                // out += p1
}